// round 11
// baseline (speedup 1.0000x reference)
#include <cuda_runtime.h>
#include <cuda_bf16.h>
#include <cstdint>
#include <math.h>

#define NB 128
#define NT 8
#define ND 2048
#define NR 4
#define NV 512
#define NN 8192   // V*R*R

#define SCALE_Q 512.0f
#define ISCALE (1.0f / 262144.0f)   // 1/(512*512)
#define PITCHB 164                  // bytes per n-row of B smem (41 words, odd)

// ---------------- scratch (no allocation allowed) ----------------
__device__ unsigned g_xbar8[NB * ND / 4];   // int8-quantized mean, packed 4/word
__device__ float g_alpha[NB * NR];
__device__ float g_beta[NB * NR];
__device__ float g_core[NB * NN];           // |xbar @ w_vocab| (scaled back to fp32)
__device__ float g_marg[NB * 16];           // sum_v core (atomic-accumulated)
__device__ float g_loss[NB];
__device__ int g_done_cnt;                  // zero-init; self-resetting

__device__ __forceinline__ unsigned pack4_s8(float x0, float x1, float x2, float x3) {
  // clamp, round-to-nearest int, pack low bytes (k ascending in byte order)
  int i0 = __float2int_rn(fminf(fmaxf(x0, -127.f), 127.f));
  int i1 = __float2int_rn(fminf(fmaxf(x1, -127.f), 127.f));
  int i2 = __float2int_rn(fminf(fmaxf(x2, -127.f), 127.f));
  int i3 = __float2int_rn(fminf(fmaxf(x3, -127.f), 127.f));
  unsigned lo = __byte_perm((unsigned)i0, (unsigned)i1, 0x0040);
  unsigned hi = __byte_perm((unsigned)i2, (unsigned)i3, 0x0040);
  return __byte_perm(lo, hi, 0x5410);
}

// =================================================================
// Kernel A: xbar = mean_t(input_embs) -> int8 (scale 512),
// alpha/beta = |xbar @ w_{a,b}| (fp32 exact). Zeroes g_marg.
// grid=128, 512 threads, each thread owns 4 contiguous d's.
// =================================================================
__global__ __launch_bounds__(512) void prep_kernel(
    const float* __restrict__ x, const float* __restrict__ wa,
    const float* __restrict__ wb) {
  const int b = blockIdx.x;
  const int tid = threadIdx.x;
  const int lane = tid & 31;
  const int warp = tid >> 5;
  const int d4 = tid * 4;                      // 512*4 = 2048
  const float* xb = x + (size_t)b * NT * ND + d4;

  if (tid < 16) g_marg[b * 16 + tid] = 0.f;

  float4 v[NT];
#pragma unroll
  for (int t = 0; t < NT; t++)
    v[t] = *reinterpret_cast<const float4*>(xb + t * ND);
  float4 s4;
  s4.x = (((v[0].x + v[1].x) + (v[2].x + v[3].x)) +
          ((v[4].x + v[5].x) + (v[6].x + v[7].x))) * 0.125f;
  s4.y = (((v[0].y + v[1].y) + (v[2].y + v[3].y)) +
          ((v[4].y + v[5].y) + (v[6].y + v[7].y))) * 0.125f;
  s4.z = (((v[0].z + v[1].z) + (v[2].z + v[3].z)) +
          ((v[4].z + v[5].z) + (v[6].z + v[7].z))) * 0.125f;
  s4.w = (((v[0].w + v[1].w) + (v[2].w + v[3].w)) +
          ((v[4].w + v[5].w) + (v[6].w + v[7].w))) * 0.125f;

  // quantize xbar -> int8 word
  g_xbar8[(b * ND + d4) >> 2] =
      pack4_s8(s4.x * SCALE_Q, s4.y * SCALE_Q, s4.z * SCALE_Q, s4.w * SCALE_Q);

  // alpha/beta partials from exact fp32 xbar
  float p[8] = {0.f, 0.f, 0.f, 0.f, 0.f, 0.f, 0.f, 0.f};
#pragma unroll
  for (int q = 0; q < 4; q++) {
    const float sd = (&s4.x)[q];
    float4 a4 = *reinterpret_cast<const float4*>(wa + (d4 + q) * 4);
    float4 b4 = *reinterpret_cast<const float4*>(wb + (d4 + q) * 4);
    p[0] += sd * a4.x; p[1] += sd * a4.y; p[2] += sd * a4.z; p[3] += sd * a4.w;
    p[4] += sd * b4.x; p[5] += sd * b4.y; p[6] += sd * b4.z; p[7] += sd * b4.w;
  }

  __shared__ float sred[16][8];
#pragma unroll
  for (int q = 0; q < 8; q++) {
    float vv = p[q];
#pragma unroll
    for (int o = 16; o; o >>= 1) vv += __shfl_xor_sync(0xFFFFFFFFu, vv, o);
    if (lane == 0) sred[warp][q] = vv;
  }
  __syncthreads();
  if (tid < 8) {
    float s = 0.f;
#pragma unroll
    for (int w = 0; w < 16; w++) s += sred[w][tid];
    s = fabsf(s);
    if (tid < 4) g_alpha[b * 4 + tid] = s;
    else         g_beta[b * 4 + (tid - 4)] = s;
  }
}

// =================================================================
// Kernel B: core = |xbar @ wv| via int8 IMMA m16n8k32 (s32 acc)
// 128 blocks (BN=64), 256 threads (8 warps: 4 in M x 2 in N)
// BM=128, BN=64, BK=64, double-buffered smem + depth-1 reg prefetch.
// A: k-major smem (pitch 64B, 16B-chunk XOR swizzle), ldmatrix frags.
// B: n-major smem (pitch 164B, odd-word -> conflict-free), LDS.32 frags.
// Epilogue: |.|*ISCALE store + atomicAdd partial marg sums.
// =================================================================
__device__ __forceinline__ void ldsm_x4(unsigned& r0, unsigned& r1,
                                        unsigned& r2, unsigned& r3,
                                        unsigned addr) {
  asm volatile("ldmatrix.sync.aligned.m8n8.x4.shared.b16 {%0,%1,%2,%3}, [%4];"
               : "=r"(r0), "=r"(r1), "=r"(r2), "=r"(r3) : "r"(addr));
}
__device__ __forceinline__ void imma16832(int& c0, int& c1, int& c2, int& c3,
                                          unsigned a0, unsigned a1, unsigned a2,
                                          unsigned a3, unsigned b0, unsigned b1) {
  asm volatile(
      "mma.sync.aligned.m16n8k32.row.col.s32.s8.s8.s32 "
      "{%0,%1,%2,%3}, {%4,%5,%6,%7}, {%8,%9}, {%0,%1,%2,%3};"
      : "+r"(c0), "+r"(c1), "+r"(c2), "+r"(c3)
      : "r"(a0), "r"(a1), "r"(a2), "r"(a3), "r"(b0), "r"(b1));
}

#define A_STAGE 8192          // 128 rows x 64 B
#define B_STAGE (64 * PITCHB) // 64 n-rows x 164 B = 10496

__global__ __launch_bounds__(256, 1) void gemm_kernel(const float* __restrict__ wv) {
  __shared__ __align__(16) unsigned char Ash[2 * A_STAGE];   // 16 KB
  __shared__ __align__(16) unsigned char Bsh[2 * B_STAGE];   // 20.5 KB

  const int tid = threadIdx.x;
  const int lane = tid & 31;
  const int warp = tid >> 5;
  const int wm = warp & 3;   // M group: rows 32*wm..
  const int wn = warp >> 2;  // N group: cols 32*wn..
  const int n0 = blockIdx.x * 64;

  int acc[2][4][4];
#pragma unroll
  for (int mi = 0; mi < 2; mi++)
#pragma unroll
    for (int g = 0; g < 4; g++)
#pragma unroll
      for (int q = 0; q < 4; q++) acc[mi][g][q] = 0;

  const unsigned aBase = (unsigned)__cvta_generic_to_shared(Ash);
  const unsigned bBase = (unsigned)__cvta_generic_to_shared(Bsh);

  // staging registers
  uint4 aS[2];
  float bS[16];
  const int nloc = tid & 63;       // B: n within tile
  const int kb = tid >> 6;         // B: which 16-k block (0..3)

  auto ldg = [&](int it) {
    const int k0 = it * 64;
    // A: 2 x uint4 (16 int8 k-values each)
#pragma unroll
    for (int i = 0; i < 2; i++) {
      int idx = tid + 256 * i;
      int row = idx >> 2, ch = idx & 3;
      aS[i] = *reinterpret_cast<const uint4*>(
          &g_xbar8[(row * ND + k0 + 16 * ch) >> 2]);
    }
    // B: 16 k-vectorized coalesced LDG.32 (fixed n, consecutive k)
    const float* src = wv + (size_t)(k0 + 16 * kb) * NN + n0 + nloc;
#pragma unroll
    for (int j = 0; j < 16; j++) bS[j] = src[j * NN];
  };

  auto sts = [&](int buf) {
    // A: swizzled 16B chunks (chunk c at row r -> c ^ ((r>>1)&3))
#pragma unroll
    for (int i = 0; i < 2; i++) {
      int idx = tid + 256 * i;
      int row = idx >> 2, ch = idx & 3;
      int sw = ch ^ ((row >> 1) & 3);
      *reinterpret_cast<uint4*>(&Ash[buf * A_STAGE + row * 64 + 16 * sw]) = aS[i];
    }
    // B: quantize + pack in-thread, n-major pitch 164 (conflict-free)
#pragma unroll
    for (int c4 = 0; c4 < 4; c4++) {
      unsigned w = pack4_s8(bS[4 * c4 + 0] * SCALE_Q, bS[4 * c4 + 1] * SCALE_Q,
                            bS[4 * c4 + 2] * SCALE_Q, bS[4 * c4 + 3] * SCALE_Q);
      *reinterpret_cast<unsigned*>(
          &Bsh[buf * B_STAGE + nloc * PITCHB + 16 * kb + 4 * c4]) = w;
    }
  };

  auto load_frags = [&](int buf, int ks, unsigned a[2][4], unsigned bf[4][2]) {
    // A fragments via ldmatrix x4 (tiles: rows0-7/k0-15, rows8-15/k0-15,
    //                                      rows0-7/k16-31, rows8-15/k16-31)
#pragma unroll
    for (int mi = 0; mi < 2; mi++) {
      int row = wm * 32 + mi * 16 + ((lane >> 3) & 1) * 8 + (lane & 7);
      int ch = 2 * ks + (lane >> 4);
      unsigned addr = aBase + buf * A_STAGE + row * 64 +
                      16 * (ch ^ ((row >> 1) & 3));
      ldsm_x4(a[mi][0], a[mi][1], a[mi][2], a[mi][3], addr);
    }
    // B fragments via plain LDS.32 (pitch 41 words -> conflict-free)
#pragma unroll
    for (int g = 0; g < 4; g++) {
      int nn = wn * 32 + g * 8 + (lane >> 2);
      const unsigned char* p =
          &Bsh[buf * B_STAGE + nn * PITCHB + 32 * ks + 4 * (lane & 3)];
      bf[g][0] = *reinterpret_cast<const unsigned*>(p);
      bf[g][1] = *reinterpret_cast<const unsigned*>(p + 16);
    }
  };

  auto compute = [&](int buf) {
    unsigned a[2][2][4], bf[2][4][2];     // double-buffered fragments
    load_frags(buf, 0, a[0], bf[0]);
#pragma unroll
    for (int ks = 0; ks < 2; ks++) {
      const int cur = ks & 1;
      if (ks < 1) load_frags(buf, ks + 1, a[cur ^ 1], bf[cur ^ 1]);
#pragma unroll
      for (int mi = 0; mi < 2; mi++)
#pragma unroll
        for (int g = 0; g < 4; g++)
          imma16832(acc[mi][g][0], acc[mi][g][1], acc[mi][g][2], acc[mi][g][3],
                    a[cur][mi][0], a[cur][mi][1], a[cur][mi][2], a[cur][mi][3],
                    bf[cur][g][0], bf[cur][g][1]);
    }
  };

  ldg(0);
  sts(0);
  __syncthreads();
#pragma unroll 1
  for (int it = 0; it < 32; it++) {
    const int buf = it & 1;
    if (it < 31) ldg(it + 1);           // depth-1 prefetch (proven)
    compute(buf);
    if (it < 31) {
      sts(buf ^ 1);
      __syncthreads();
    }
  }

  // epilogue: |.|*ISCALE, store fp32 core, accumulate marg partials
  const int iblk = n0 >> 11;            // i index (R dim), constant per CTA
#pragma unroll
  for (int mi = 0; mi < 2; mi++) {
    const int m = wm * 32 + mi * 16 + (lane >> 2);
    const int j0 = (2 * (lane & 3)) & 3;  // j of even col; j0+1 for odd col
    float pj0_a = 0.f, pj1_a = 0.f, pj0_b = 0.f, pj1_b = 0.f;
#pragma unroll
    for (int g = 0; g < 4; g++) {
      int n = n0 + wn * 32 + g * 8 + (lane & 3) * 2;
      float v0 = fabsf((float)acc[mi][g][0] * ISCALE);
      float v1 = fabsf((float)acc[mi][g][1] * ISCALE);
      float v2 = fabsf((float)acc[mi][g][2] * ISCALE);
      float v3 = fabsf((float)acc[mi][g][3] * ISCALE);
      *reinterpret_cast<float2*>(&g_core[(size_t)m * NN + n]) = make_float2(v0, v1);
      *reinterpret_cast<float2*>(&g_core[(size_t)(m + 8) * NN + n]) = make_float2(v2, v3);
      pj0_a += v0; pj1_a += v1; pj0_b += v2; pj1_b += v3;
    }
    atomicAdd(&g_marg[m * 16 + iblk * 4 + j0], pj0_a);
    atomicAdd(&g_marg[m * 16 + iblk * 4 + j0 + 1], pj1_a);
    atomicAdd(&g_marg[(m + 8) * 16 + iblk * 4 + j0], pj0_b);
    atomicAdd(&g_marg[(m + 8) * 16 + iblk * 4 + j0 + 1], pj1_b);
  }
}

// =================================================================
// Kernel C: per-batch label gather, 4x4 chains, loss_b,
// fused last-block mean reduction -> out[0]
// =================================================================
__global__ __launch_bounds__(128) void finalize_kernel(
    const int* __restrict__ labels, float* __restrict__ out) {
  const int b = blockIdx.x;
  const int tid = threadIdx.x;
  const float* cb = g_core + (size_t)b * NN;

  __shared__ float sel[NT][16];
  __shared__ int slab[NT];

  if (tid < NT) slab[tid] = labels[b * NT + tid];
  __syncthreads();
  if (tid < NT * 16) {
    const int t = tid >> 4, q = tid & 15;
    sel[t][q] = cb[(q >> 2) * (NV * NR) + slab[t] * NR + (q & 3)];
  }
  __syncthreads();

  if (tid == 0) {
    float res[16], tmp[16];
#pragma unroll
    for (int q = 0; q < 16; q++) res[q] = sel[0][q];
    for (int t = 1; t < NT; t++) {
#pragma unroll
      for (int ii = 0; ii < 4; ii++)
#pragma unroll
        for (int jj = 0; jj < 4; jj++) {
          float a2 = 0.f;
#pragma unroll
          for (int kk = 0; kk < 4; kk++) a2 += res[ii * 4 + kk] * sel[t][kk * 4 + jj];
          tmp[ii * 4 + jj] = a2;
        }
#pragma unroll
      for (int q = 0; q < 16; q++) res[q] = tmp[q];
    }
    const float* al = g_alpha + b * 4;
    const float* be = g_beta + b * 4;
    float u = 0.f;
#pragma unroll
    for (int ii = 0; ii < 4; ii++)
#pragma unroll
      for (int jj = 0; jj < 4; jj++) u += al[ii] * res[ii * 4 + jj] * be[jj];

    float marg[16], zc[16];
#pragma unroll
    for (int q = 0; q < 16; q++) { marg[q] = g_marg[b * 16 + q]; zc[q] = marg[q]; }
    for (int t = 0; t < NT; t++) {   // zc = marg^(T+1)
#pragma unroll
      for (int ii = 0; ii < 4; ii++)
#pragma unroll
        for (int jj = 0; jj < 4; jj++) {
          float a2 = 0.f;
#pragma unroll
          for (int kk = 0; kk < 4; kk++) a2 += zc[ii * 4 + kk] * marg[kk * 4 + jj];
          tmp[ii * 4 + jj] = a2;
        }
#pragma unroll
      for (int q = 0; q < 16; q++) zc[q] = tmp[q];
    }
    float z = 0.f;
#pragma unroll
    for (int ii = 0; ii < 4; ii++)
#pragma unroll
      for (int jj = 0; jj < 4; jj++) z += al[ii] * zc[ii * 4 + jj] * be[jj];

    g_loss[b] = logf(z) - logf(u);   // = -log(u/z)
  }

  // ---- fused mean reduction: last block to finish does it ----
  __shared__ int is_last;
  if (tid == 0) {
    __threadfence();
    int prev = atomicAdd(&g_done_cnt, 1);
    is_last = (prev == NB - 1);
  }
  __syncthreads();
  if (is_last) {
    __threadfence();
    float v = g_loss[tid];
#pragma unroll
    for (int o = 16; o; o >>= 1) v += __shfl_xor_sync(0xFFFFFFFFu, v, o);
    __shared__ float sw[4];
    if ((tid & 31) == 0) sw[tid >> 5] = v;
    __syncthreads();
    if (tid == 0) {
      out[0] = (sw[0] + sw[1] + sw[2] + sw[3]) * (1.0f / 128.0f);
      atomicExch(&g_done_cnt, 0);   // reset for next graph replay
    }
  }
}

// =================================================================
extern "C" void kernel_launch(void* const* d_in, const int* in_sizes, int n_in,
                              void* d_out, int out_size) {
  const float* x      = (const float*)d_in[0];   // [128, 8, 2048]
  const int*   labels = (const int*)  d_in[1];   // [128, 8]
  const float* wa     = (const float*)d_in[2];   // [2048, 4]
  const float* wb     = (const float*)d_in[3];   // [2048, 4]
  const float* wv     = (const float*)d_in[4];   // [2048, 8192]
  float* out = (float*)d_out;

  prep_kernel<<<NB, 512>>>(x, wa, wb);
  gemm_kernel<<<NN / 64, 256>>>(wv);
  finalize_kernel<<<NB, 128>>>(labels, out);
}

// round 12
// speedup vs baseline: 1.5170x; 1.5170x over previous
#include <cuda_runtime.h>
#include <cuda_bf16.h>
#include <cstdint>
#include <math.h>

#define NB 128
#define NT 8
#define ND 2048
#define NR 4
#define NV 512
#define NN 8192   // V*R*R

// ---------------- scratch (no allocation allowed) ----------------
__device__ __nv_bfloat16 g_xbar[NB * ND];   // mean over T, bf16
__device__ float g_alpha[NB * NR];
__device__ float g_beta[NB * NR];
__device__ float g_core[NB * NN];           // |xbar @ w_vocab|
__device__ float g_loss[NB];
__device__ int g_done_cnt;                  // zero-init; self-resetting

// =================================================================
// Kernel A: xbar = mean_t(input_embs), alpha/beta = |xbar @ w_{a,b}|
// 512 threads / batch, float4 everywhere (proven 6.9us).
// =================================================================
__global__ __launch_bounds__(512) void prep_kernel(
    const float* __restrict__ x, const float* __restrict__ wa,
    const float* __restrict__ wb) {
  const int b = blockIdx.x;
  const int tid = threadIdx.x;
  const int lane = tid & 31;
  const int warp = tid >> 5;
  const int d4 = tid * 4;                      // 512*4 = 2048
  const float* xb = x + (size_t)b * NT * ND + d4;

  // ---- mean over T (8 independent LDG.128) ----
  float4 v[NT];
#pragma unroll
  for (int t = 0; t < NT; t++)
    v[t] = *reinterpret_cast<const float4*>(xb + t * ND);
  float4 s4;
  s4.x = (((v[0].x + v[1].x) + (v[2].x + v[3].x)) +
          ((v[4].x + v[5].x) + (v[6].x + v[7].x))) * 0.125f;
  s4.y = (((v[0].y + v[1].y) + (v[2].y + v[3].y)) +
          ((v[4].y + v[5].y) + (v[6].y + v[7].y))) * 0.125f;
  s4.z = (((v[0].z + v[1].z) + (v[2].z + v[3].z)) +
          ((v[4].z + v[5].z) + (v[6].z + v[7].z))) * 0.125f;
  s4.w = (((v[0].w + v[1].w) + (v[2].w + v[3].w)) +
          ((v[4].w + v[5].w) + (v[6].w + v[7].w))) * 0.125f;

  __nv_bfloat162 lo = __floats2bfloat162_rn(s4.x, s4.y);
  __nv_bfloat162 hi = __floats2bfloat162_rn(s4.z, s4.w);
  uint2 packed;
  packed.x = *reinterpret_cast<unsigned*>(&lo);
  packed.y = *reinterpret_cast<unsigned*>(&hi);
  *reinterpret_cast<uint2*>(&g_xbar[b * ND + d4]) = packed;

  // ---- alpha/beta partials over this thread's 4 d's ----
  float p[8] = {0.f, 0.f, 0.f, 0.f, 0.f, 0.f, 0.f, 0.f};
#pragma unroll
  for (int q = 0; q < 4; q++) {
    const float sd = (&s4.x)[q];
    float4 a4 = *reinterpret_cast<const float4*>(wa + (d4 + q) * 4);
    float4 b4 = *reinterpret_cast<const float4*>(wb + (d4 + q) * 4);
    p[0] += sd * a4.x; p[1] += sd * a4.y; p[2] += sd * a4.z; p[3] += sd * a4.w;
    p[4] += sd * b4.x; p[5] += sd * b4.y; p[6] += sd * b4.z; p[7] += sd * b4.w;
  }

  __shared__ float sred[16][8];
#pragma unroll
  for (int q = 0; q < 8; q++) {
    float vv = p[q];
#pragma unroll
    for (int o = 16; o; o >>= 1) vv += __shfl_xor_sync(0xFFFFFFFFu, vv, o);
    if (lane == 0) sred[warp][q] = vv;
  }
  __syncthreads();
  if (tid < 8) {
    float s = 0.f;
#pragma unroll
    for (int w = 0; w < 16; w++) s += sred[w][tid];
    s = fabsf(s);
    if (tid < 4) g_alpha[b * 4 + tid] = s;
    else         g_beta[b * 4 + (tid - 4)] = s;
  }
}

// =================================================================
// Kernel B: core = |xbar[128,2048] @ wv[2048,8192]|  (bf16 HMMA)
// EXACT R1 structure (fastest measured GEMM): 128 blocks (BN=64),
// 256 threads (8 warps: 4 in M x 2 in N), BM=128, BN=64, BK=64,
// double-buffered smem + depth-1 reg prefetch, per-ks frag loads.
// =================================================================
__device__ __forceinline__ void ldsm_x4(unsigned& r0, unsigned& r1,
                                        unsigned& r2, unsigned& r3,
                                        unsigned addr) {
  asm volatile("ldmatrix.sync.aligned.m8n8.x4.shared.b16 {%0,%1,%2,%3}, [%4];"
               : "=r"(r0), "=r"(r1), "=r"(r2), "=r"(r3) : "r"(addr));
}
__device__ __forceinline__ void ldsm_x4_t(unsigned& r0, unsigned& r1,
                                          unsigned& r2, unsigned& r3,
                                          unsigned addr) {
  asm volatile("ldmatrix.sync.aligned.m8n8.x4.trans.shared.b16 {%0,%1,%2,%3}, [%4];"
               : "=r"(r0), "=r"(r1), "=r"(r2), "=r"(r3) : "r"(addr));
}
__device__ __forceinline__ void mma16816(float& c0, float& c1, float& c2, float& c3,
                                         unsigned a0, unsigned a1, unsigned a2,
                                         unsigned a3, unsigned b0, unsigned b1) {
  asm volatile(
      "mma.sync.aligned.m16n8k16.row.col.f32.bf16.bf16.f32 "
      "{%0,%1,%2,%3}, {%4,%5,%6,%7}, {%8,%9}, {%0,%1,%2,%3};"
      : "+f"(c0), "+f"(c1), "+f"(c2), "+f"(c3)
      : "r"(a0), "r"(a1), "r"(a2), "r"(a3), "r"(b0), "r"(b1));
}

__global__ __launch_bounds__(256, 1) void gemm_kernel(const float* __restrict__ wv) {
  __shared__ __align__(16) __nv_bfloat16 Ash[2][128 * 64];  // 32 KB
  __shared__ __align__(16) __nv_bfloat16 Bsh[2][64 * 64];   // 16 KB

  const int tid = threadIdx.x;
  const int lane = tid & 31;
  const int warp = tid >> 5;
  const int wm = warp & 3;   // M group: rows 32*wm..
  const int wn = warp >> 2;  // N group: cols 32*wn..
  const int n0 = blockIdx.x * 64;

  float c[2][4][4];
#pragma unroll
  for (int mi = 0; mi < 2; mi++)
#pragma unroll
    for (int ni = 0; ni < 4; ni++)
#pragma unroll
      for (int q = 0; q < 4; q++) c[mi][ni][q] = 0.f;

  const unsigned aBase = (unsigned)__cvta_generic_to_shared(&Ash[0][0]);
  const unsigned bBase = (unsigned)__cvta_generic_to_shared(&Bsh[0][0]);
  const int lm = lane & 15;
  const int lh = lane >> 4;  // 0/1

  uint4 ar[4];
  float4 br[4];

  auto ldg = [&](int it) {
    const int k0 = it * 64;
#pragma unroll
    for (int i = 0; i < 4; i++) {
      int idx = tid + 256 * i;
      int row = idx >> 3, ch = idx & 7;       // A: 128 rows x 8 chunks of 16B
      ar[i] = *reinterpret_cast<const uint4*>(&g_xbar[row * ND + k0 + ch * 8]);
    }
#pragma unroll
    for (int i = 0; i < 4; i++) {
      int idx = tid + 256 * i;
      int row = idx >> 4, f4 = idx & 15;      // B: 64 rows x 16 float4
      br[i] = *reinterpret_cast<const float4*>(wv + (size_t)(k0 + row) * NN + n0 + f4 * 4);
    }
  };
  auto sts = [&](int buf) {
#pragma unroll
    for (int i = 0; i < 4; i++) {
      int idx = tid + 256 * i;
      int row = idx >> 3, ch = idx & 7;
      int s = row * 64 + ((ch ^ (row & 7)) << 3);      // XOR swizzle, bf16 units
      *reinterpret_cast<uint4*>(&Ash[buf][s]) = ar[i];
    }
#pragma unroll
    for (int i = 0; i < 4; i++) {
      int idx = tid + 256 * i;
      int row = idx >> 4, f4 = idx & 15;
      __nv_bfloat162 lo = __floats2bfloat162_rn(br[i].x, br[i].y);
      __nv_bfloat162 hi = __floats2bfloat162_rn(br[i].z, br[i].w);
      int s = row * 64 + (((f4 >> 1) ^ (row & 7)) << 3) + (f4 & 1) * 4;
      unsigned* p = reinterpret_cast<unsigned*>(&Bsh[buf][s]);
      p[0] = *reinterpret_cast<unsigned*>(&lo);
      p[1] = *reinterpret_cast<unsigned*>(&hi);
    }
  };
  auto compute = [&](int buf) {
    const unsigned aB = aBase + buf * (128 * 64 * 2);
    const unsigned bB = bBase + buf * (64 * 64 * 2);
#pragma unroll
    for (int ks = 0; ks < 4; ks++) {
      unsigned a[2][4], bf[4][2];
#pragma unroll
      for (int mi = 0; mi < 2; mi++) {
        int mrow = wm * 32 + mi * 16 + lm;
        int kc = ks * 2 + lh;                            // 16B chunk of k
        int s = mrow * 64 + ((kc ^ (mrow & 7)) << 3);
        ldsm_x4(a[mi][0], a[mi][1], a[mi][2], a[mi][3], aB + s * 2);
      }
#pragma unroll
      for (int ni2 = 0; ni2 < 2; ni2++) {
        int kr = ks * 16 + lm;
        int nch = wn * 4 + ni2 * 2 + lh;                 // 16B chunk of n
        int s = kr * 64 + ((nch ^ (kr & 7)) << 3);
        unsigned r0, r1, r2, r3;
        ldsm_x4_t(r0, r1, r2, r3, bB + s * 2);
        bf[ni2 * 2 + 0][0] = r0; bf[ni2 * 2 + 0][1] = r1;
        bf[ni2 * 2 + 1][0] = r2; bf[ni2 * 2 + 1][1] = r3;
      }
#pragma unroll
      for (int mi = 0; mi < 2; mi++)
#pragma unroll
        for (int ni = 0; ni < 4; ni++)
          mma16816(c[mi][ni][0], c[mi][ni][1], c[mi][ni][2], c[mi][ni][3],
                   a[mi][0], a[mi][1], a[mi][2], a[mi][3],
                   bf[ni][0], bf[ni][1]);
    }
  };

  ldg(0);
  sts(0);
  __syncthreads();
#pragma unroll 1
  for (int it = 0; it < 32; it++) {
    const int buf = it & 1;
    if (it < 31) ldg(it + 1);           // depth-1 prefetch
    compute(buf);
    if (it < 31) {
      sts(buf ^ 1);
      __syncthreads();
    }
  }

  // epilogue: |.| and store fp32 core (plain stores, no atomics)
#pragma unroll
  for (int mi = 0; mi < 2; mi++) {
#pragma unroll
    for (int ni = 0; ni < 4; ni++) {
      int m = wm * 32 + mi * 16 + (lane >> 2);
      int n = n0 + wn * 32 + ni * 8 + (lane & 3) * 2;
      float2 v0 = make_float2(fabsf(c[mi][ni][0]), fabsf(c[mi][ni][1]));
      float2 v1 = make_float2(fabsf(c[mi][ni][2]), fabsf(c[mi][ni][3]));
      *reinterpret_cast<float2*>(&g_core[(size_t)m * NN + n]) = v0;
      *reinterpret_cast<float2*>(&g_core[(size_t)(m + 8) * NN + n]) = v1;
    }
  }
}

// =================================================================
// Kernel C: per-batch marg scan, label gather, 4x4 chains, loss_b,
// fused last-block mean reduction -> out[0]
// =================================================================
__global__ __launch_bounds__(128) void finalize_kernel(
    const int* __restrict__ labels, float* __restrict__ out) {
  const int b = blockIdx.x;
  const int tid = threadIdx.x;
  const float* cb = g_core + (size_t)b * NN;

  __shared__ float part[8][16];
  __shared__ float marg[16];

  const int ij = tid & 15, vs = tid >> 4;
  const int i = ij >> 2, j = ij & 3;
  float s = 0.f;
  for (int v = vs * 64; v < vs * 64 + 64; v++)
    s += cb[i * (NV * NR) + v * NR + j];
  part[vs][ij] = s;
  __syncthreads();
  if (tid < 16) {
    float m = 0.f;
#pragma unroll
    for (int w = 0; w < 8; w++) m += part[w][tid];
    marg[tid] = m;
  }
  __syncthreads();

  if (tid == 0) {
    float res[16], tmp[16], mt[16];
    int lab = labels[b * NT];
#pragma unroll
    for (int q = 0; q < 16; q++)
      res[q] = cb[(q >> 2) * (NV * NR) + lab * NR + (q & 3)];
    for (int t = 1; t < NT; t++) {
      lab = labels[b * NT + t];
#pragma unroll
      for (int q = 0; q < 16; q++)
        mt[q] = cb[(q >> 2) * (NV * NR) + lab * NR + (q & 3)];
#pragma unroll
      for (int ii = 0; ii < 4; ii++)
#pragma unroll
        for (int jj = 0; jj < 4; jj++) {
          float acc = 0.f;
#pragma unroll
          for (int kk = 0; kk < 4; kk++) acc += res[ii * 4 + kk] * mt[kk * 4 + jj];
          tmp[ii * 4 + jj] = acc;
        }
#pragma unroll
      for (int q = 0; q < 16; q++) res[q] = tmp[q];
    }
    const float* al = g_alpha + b * 4;
    const float* be = g_beta + b * 4;
    float u = 0.f;
#pragma unroll
    for (int ii = 0; ii < 4; ii++)
#pragma unroll
      for (int jj = 0; jj < 4; jj++) u += al[ii] * res[ii * 4 + jj] * be[jj];

    float zc[16];
#pragma unroll
    for (int q = 0; q < 16; q++) zc[q] = marg[q];
    for (int t = 0; t < NT; t++) {   // zc = marg^(T+1)
#pragma unroll
      for (int ii = 0; ii < 4; ii++)
#pragma unroll
        for (int jj = 0; jj < 4; jj++) {
          float acc = 0.f;
#pragma unroll
          for (int kk = 0; kk < 4; kk++) acc += zc[ii * 4 + kk] * marg[kk * 4 + jj];
          tmp[ii * 4 + jj] = acc;
        }
#pragma unroll
      for (int q = 0; q < 16; q++) zc[q] = tmp[q];
    }
    float z = 0.f;
#pragma unroll
    for (int ii = 0; ii < 4; ii++)
#pragma unroll
      for (int jj = 0; jj < 4; jj++) z += al[ii] * zc[ii * 4 + jj] * be[jj];

    g_loss[b] = logf(z) - logf(u);   // = -log(u/z)
  }

  // ---- fused mean reduction: last block to finish does it ----
  __shared__ int is_last;
  if (tid == 0) {
    __threadfence();
    int prev = atomicAdd(&g_done_cnt, 1);
    is_last = (prev == NB - 1);
  }
  __syncthreads();
  if (is_last) {
    __threadfence();
    float v = g_loss[tid];
#pragma unroll
    for (int o = 16; o; o >>= 1) v += __shfl_xor_sync(0xFFFFFFFFu, v, o);
    __shared__ float sw[4];
    if ((tid & 31) == 0) sw[tid >> 5] = v;
    __syncthreads();
    if (tid == 0) {
      out[0] = (sw[0] + sw[1] + sw[2] + sw[3]) * (1.0f / 128.0f);
      atomicExch(&g_done_cnt, 0);   // reset for next graph replay
    }
  }
}

// =================================================================
extern "C" void kernel_launch(void* const* d_in, const int* in_sizes, int n_in,
                              void* d_out, int out_size) {
  const float* x      = (const float*)d_in[0];   // [128, 8, 2048]
  const int*   labels = (const int*)  d_in[1];   // [128, 8]
  const float* wa     = (const float*)d_in[2];   // [2048, 4]
  const float* wb     = (const float*)d_in[3];   // [2048, 4]
  const float* wv     = (const float*)d_in[4];   // [2048, 8192]
  float* out = (float*)d_out;

  prep_kernel<<<NB, 512>>>(x, wa, wb);
  gemm_kernel<<<NN / 64, 256>>>(wv);
  finalize_kernel<<<NB, 128>>>(labels, out);
}

// round 14
// speedup vs baseline: 1.5893x; 1.0476x over previous
#include <cuda_runtime.h>
#include <cuda_bf16.h>
#include <cstdint>
#include <math.h>

#define NB 128
#define NT 8
#define ND 2048
#define NR 4
#define NV 512
#define NN 8192   // V*R*R

// ---------------- scratch (no allocation allowed) ----------------
__device__ __nv_bfloat16 g_xbar[NB * ND];   // mean over T, bf16
__device__ float g_alpha[NB * NR];
__device__ float g_beta[NB * NR];
__device__ float g_part0[NB * NN];          // signed partial (K 0..1023)
__device__ float g_part1[NB * NN];          // signed partial (K 1024..2047)
__device__ float g_loss[NB];
__device__ int g_done_cnt;                  // zero-init; self-resetting

// =================================================================
// Kernel A: xbar = mean_t(input_embs), alpha/beta = |xbar @ w_{a,b}|
// 512 threads / batch, float4 everywhere (proven 6.8us).
// =================================================================
__global__ __launch_bounds__(512) void prep_kernel(
    const float* __restrict__ x, const float* __restrict__ wa,
    const float* __restrict__ wb) {
  const int b = blockIdx.x;
  const int tid = threadIdx.x;
  const int lane = tid & 31;
  const int warp = tid >> 5;
  const int d4 = tid * 4;                      // 512*4 = 2048
  const float* xb = x + (size_t)b * NT * ND + d4;

  // ---- mean over T (8 independent LDG.128) ----
  float4 v[NT];
#pragma unroll
  for (int t = 0; t < NT; t++)
    v[t] = *reinterpret_cast<const float4*>(xb + t * ND);
  float4 s4;
  s4.x = (((v[0].x + v[1].x) + (v[2].x + v[3].x)) +
          ((v[4].x + v[5].x) + (v[6].x + v[7].x))) * 0.125f;
  s4.y = (((v[0].y + v[1].y) + (v[2].y + v[3].y)) +
          ((v[4].y + v[5].y) + (v[6].y + v[7].y))) * 0.125f;
  s4.z = (((v[0].z + v[1].z) + (v[2].z + v[3].z)) +
          ((v[4].z + v[5].z) + (v[6].z + v[7].z))) * 0.125f;
  s4.w = (((v[0].w + v[1].w) + (v[2].w + v[3].w)) +
          ((v[4].w + v[5].w) + (v[6].w + v[7].w))) * 0.125f;

  __nv_bfloat162 lo = __floats2bfloat162_rn(s4.x, s4.y);
  __nv_bfloat162 hi = __floats2bfloat162_rn(s4.z, s4.w);
  uint2 packed;
  packed.x = *reinterpret_cast<unsigned*>(&lo);
  packed.y = *reinterpret_cast<unsigned*>(&hi);
  *reinterpret_cast<uint2*>(&g_xbar[b * ND + d4]) = packed;

  // ---- alpha/beta partials over this thread's 4 d's ----
  float p[8] = {0.f, 0.f, 0.f, 0.f, 0.f, 0.f, 0.f, 0.f};
#pragma unroll
  for (int q = 0; q < 4; q++) {
    const float sd = (&s4.x)[q];
    float4 a4 = *reinterpret_cast<const float4*>(wa + (d4 + q) * 4);
    float4 b4 = *reinterpret_cast<const float4*>(wb + (d4 + q) * 4);
    p[0] += sd * a4.x; p[1] += sd * a4.y; p[2] += sd * a4.z; p[3] += sd * a4.w;
    p[4] += sd * b4.x; p[5] += sd * b4.y; p[6] += sd * b4.z; p[7] += sd * b4.w;
  }

  __shared__ float sred[16][8];
#pragma unroll
  for (int q = 0; q < 8; q++) {
    float vv = p[q];
#pragma unroll
    for (int o = 16; o; o >>= 1) vv += __shfl_xor_sync(0xFFFFFFFFu, vv, o);
    if (lane == 0) sred[warp][q] = vv;
  }
  __syncthreads();
  if (tid < 8) {
    float s = 0.f;
#pragma unroll
    for (int w = 0; w < 16; w++) s += sred[w][tid];
    s = fabsf(s);
    if (tid < 4) g_alpha[b * 4 + tid] = s;
    else         g_beta[b * 4 + (tid - 4)] = s;
  }
}

// =================================================================
// Kernel B: split-K GEMM.  part_kt = xbar[:, kt*1024:(kt+1)*1024]
//                                   @ wv[kt*1024:(kt+1)*1024, :]
// 256 blocks (128 n-tiles x 2 k-halves), 256 threads, 2 CTAs/SM.
// Inner loop identical to the proven R1 structure; 16 iterations.
// Stores SIGNED partials; abs happens in finalize after the add.
// =================================================================
__device__ __forceinline__ void ldsm_x4(unsigned& r0, unsigned& r1,
                                        unsigned& r2, unsigned& r3,
                                        unsigned addr) {
  asm volatile("ldmatrix.sync.aligned.m8n8.x4.shared.b16 {%0,%1,%2,%3}, [%4];"
               : "=r"(r0), "=r"(r1), "=r"(r2), "=r"(r3) : "r"(addr));
}
__device__ __forceinline__ void ldsm_x4_t(unsigned& r0, unsigned& r1,
                                          unsigned& r2, unsigned& r3,
                                          unsigned addr) {
  asm volatile("ldmatrix.sync.aligned.m8n8.x4.trans.shared.b16 {%0,%1,%2,%3}, [%4];"
               : "=r"(r0), "=r"(r1), "=r"(r2), "=r"(r3) : "r"(addr));
}
__device__ __forceinline__ void mma16816(float& c0, float& c1, float& c2, float& c3,
                                         unsigned a0, unsigned a1, unsigned a2,
                                         unsigned a3, unsigned b0, unsigned b1) {
  asm volatile(
      "mma.sync.aligned.m16n8k16.row.col.f32.bf16.bf16.f32 "
      "{%0,%1,%2,%3}, {%4,%5,%6,%7}, {%8,%9}, {%0,%1,%2,%3};"
      : "+f"(c0), "+f"(c1), "+f"(c2), "+f"(c3)
      : "r"(a0), "r"(a1), "r"(a2), "r"(a3), "r"(b0), "r"(b1));
}

__global__ __launch_bounds__(256, 2) void gemm_kernel(const float* __restrict__ wv) {
  __shared__ __align__(16) __nv_bfloat16 Ash[2][128 * 64];  // 32 KB
  __shared__ __align__(16) __nv_bfloat16 Bsh[2][64 * 64];   // 16 KB

  const int tid = threadIdx.x;
  const int lane = tid & 31;
  const int warp = tid >> 5;
  const int wm = warp & 3;   // M group: rows 32*wm..
  const int wn = warp >> 2;  // N group: cols 32*wn..
  const int bid = blockIdx.x;
  const int kt = bid >> 7;                 // k-half: 0 or 1
  const int n0 = (bid & 127) * 64;
  const int kbase = kt * 16;               // iteration offset (64 k per it)
  float* outbuf = kt ? g_part1 : g_part0;

  float c[2][4][4];
#pragma unroll
  for (int mi = 0; mi < 2; mi++)
#pragma unroll
    for (int ni = 0; ni < 4; ni++)
#pragma unroll
      for (int q = 0; q < 4; q++) c[mi][ni][q] = 0.f;

  const unsigned aBase = (unsigned)__cvta_generic_to_shared(&Ash[0][0]);
  const unsigned bBase = (unsigned)__cvta_generic_to_shared(&Bsh[0][0]);
  const int lm = lane & 15;
  const int lh = lane >> 4;  // 0/1

  uint4 ar[4];
  float4 br[4];

  auto ldg = [&](int it) {
    const int k0 = (kbase + it) * 64;
#pragma unroll
    for (int i = 0; i < 4; i++) {
      int idx = tid + 256 * i;
      int row = idx >> 3, ch = idx & 7;       // A: 128 rows x 8 chunks of 16B
      ar[i] = *reinterpret_cast<const uint4*>(&g_xbar[row * ND + k0 + ch * 8]);
    }
#pragma unroll
    for (int i = 0; i < 4; i++) {
      int idx = tid + 256 * i;
      int row = idx >> 4, f4 = idx & 15;      // B: 64 rows x 16 float4
      br[i] = *reinterpret_cast<const float4*>(wv + (size_t)(k0 + row) * NN + n0 + f4 * 4);
    }
  };
  auto sts = [&](int buf) {
#pragma unroll
    for (int i = 0; i < 4; i++) {
      int idx = tid + 256 * i;
      int row = idx >> 3, ch = idx & 7;
      int s = row * 64 + ((ch ^ (row & 7)) << 3);      // XOR swizzle, bf16 units
      *reinterpret_cast<uint4*>(&Ash[buf][s]) = ar[i];
    }
#pragma unroll
    for (int i = 0; i < 4; i++) {
      int idx = tid + 256 * i;
      int row = idx >> 4, f4 = idx & 15;
      __nv_bfloat162 lo = __floats2bfloat162_rn(br[i].x, br[i].y);
      __nv_bfloat162 hi = __floats2bfloat162_rn(br[i].z, br[i].w);
      int s = row * 64 + (((f4 >> 1) ^ (row & 7)) << 3) + (f4 & 1) * 4;
      unsigned* p = reinterpret_cast<unsigned*>(&Bsh[buf][s]);
      p[0] = *reinterpret_cast<unsigned*>(&lo);
      p[1] = *reinterpret_cast<unsigned*>(&hi);
    }
  };
  auto compute = [&](int buf) {
    const unsigned aB = aBase + buf * (128 * 64 * 2);
    const unsigned bB = bBase + buf * (64 * 64 * 2);
#pragma unroll
    for (int ks = 0; ks < 4; ks++) {
      unsigned a[2][4], bf[4][2];
#pragma unroll
      for (int mi = 0; mi < 2; mi++) {
        int mrow = wm * 32 + mi * 16 + lm;
        int kc = ks * 2 + lh;                            // 16B chunk of k
        int s = mrow * 64 + ((kc ^ (mrow & 7)) << 3);
        ldsm_x4(a[mi][0], a[mi][1], a[mi][2], a[mi][3], aB + s * 2);
      }
#pragma unroll
      for (int ni2 = 0; ni2 < 2; ni2++) {
        int kr = ks * 16 + lm;
        int nch = wn * 4 + ni2 * 2 + lh;                 // 16B chunk of n
        int s = kr * 64 + ((nch ^ (kr & 7)) << 3);
        unsigned r0, r1, r2, r3;
        ldsm_x4_t(r0, r1, r2, r3, bB + s * 2);
        bf[ni2 * 2 + 0][0] = r0; bf[ni2 * 2 + 0][1] = r1;
        bf[ni2 * 2 + 1][0] = r2; bf[ni2 * 2 + 1][1] = r3;
      }
#pragma unroll
      for (int mi = 0; mi < 2; mi++)
#pragma unroll
        for (int ni = 0; ni < 4; ni++)
          mma16816(c[mi][ni][0], c[mi][ni][1], c[mi][ni][2], c[mi][ni][3],
                   a[mi][0], a[mi][1], a[mi][2], a[mi][3],
                   bf[ni][0], bf[ni][1]);
    }
  };

  ldg(0);
  sts(0);
  __syncthreads();
#pragma unroll 1
  for (int it = 0; it < 16; it++) {
    const int buf = it & 1;
    if (it < 15) ldg(it + 1);           // depth-1 prefetch
    compute(buf);
    if (it < 15) {
      sts(buf ^ 1);
      __syncthreads();
    }
  }

  // epilogue: store SIGNED partials (abs happens after the k-halves add)
#pragma unroll
  for (int mi = 0; mi < 2; mi++) {
#pragma unroll
    for (int ni = 0; ni < 4; ni++) {
      int m = wm * 32 + mi * 16 + (lane >> 2);
      int n = n0 + wn * 32 + ni * 8 + (lane & 3) * 2;
      *reinterpret_cast<float2*>(&outbuf[(size_t)m * NN + n]) =
          make_float2(c[mi][ni][0], c[mi][ni][1]);
      *reinterpret_cast<float2*>(&outbuf[(size_t)(m + 8) * NN + n]) =
          make_float2(c[mi][ni][2], c[mi][ni][3]);
    }
  }
}

// =================================================================
// Kernel C: per-batch marg scan (|p0+p1|), label gather, 4x4 chains,
// loss_b, fused last-block mean reduction -> out[0]
// =================================================================
__global__ __launch_bounds__(128) void finalize_kernel(
    const int* __restrict__ labels, float* __restrict__ out) {
  const int b = blockIdx.x;
  const int tid = threadIdx.x;
  const float* p0 = g_part0 + (size_t)b * NN;
  const float* p1 = g_part1 + (size_t)b * NN;

  __shared__ float part[8][16];
  __shared__ float marg[16];

  const int ij = tid & 15, vs = tid >> 4;
  const int i = ij >> 2, j = ij & 3;
  float s = 0.f;
  for (int v = vs * 64; v < vs * 64 + 64; v++) {
    int idx = i * (NV * NR) + v * NR + j;
    s += fabsf(p0[idx] + p1[idx]);
  }
  part[vs][ij] = s;
  __syncthreads();
  if (tid < 16) {
    float m = 0.f;
#pragma unroll
    for (int w = 0; w < 8; w++) m += part[w][tid];
    marg[tid] = m;
  }
  __syncthreads();

  if (tid == 0) {
    float res[16], tmp[16], mt[16];
    int lab = labels[b * NT];
#pragma unroll
    for (int q = 0; q < 16; q++) {
      int idx = (q >> 2) * (NV * NR) + lab * NR + (q & 3);
      res[q] = fabsf(p0[idx] + p1[idx]);
    }
    for (int t = 1; t < NT; t++) {
      lab = labels[b * NT + t];
#pragma unroll
      for (int q = 0; q < 16; q++) {
        int idx = (q >> 2) * (NV * NR) + lab * NR + (q & 3);
        mt[q] = fabsf(p0[idx] + p1[idx]);
      }
#pragma unroll
      for (int ii = 0; ii < 4; ii++)
#pragma unroll
        for (int jj = 0; jj < 4; jj++) {
          float acc = 0.f;
#pragma unroll
          for (int kk = 0; kk < 4; kk++) acc += res[ii * 4 + kk] * mt[kk * 4 + jj];
          tmp[ii * 4 + jj] = acc;
        }
#pragma unroll
      for (int q = 0; q < 16; q++) res[q] = tmp[q];
    }
    const float* al = g_alpha + b * 4;
    const float* be = g_beta + b * 4;
    float u = 0.f;
#pragma unroll
    for (int ii = 0; ii < 4; ii++)
#pragma unroll
      for (int jj = 0; jj < 4; jj++) u += al[ii] * res[ii * 4 + jj] * be[jj];

    float zc[16];
#pragma unroll
    for (int q = 0; q < 16; q++) zc[q] = marg[q];
    for (int t = 0; t < NT; t++) {   // zc = marg^(T+1)
#pragma unroll
      for (int ii = 0; ii < 4; ii++)
#pragma unroll
        for (int jj = 0; jj < 4; jj++) {
          float acc = 0.f;
#pragma unroll
          for (int kk = 0; kk < 4; kk++) acc += zc[ii * 4 + kk] * marg[kk * 4 + jj];
          tmp[ii * 4 + jj] = acc;
        }
#pragma unroll
      for (int q = 0; q < 16; q++) zc[q] = tmp[q];
    }
    float z = 0.f;
#pragma unroll
    for (int ii = 0; ii < 4; ii++)
#pragma unroll
      for (int jj = 0; jj < 4; jj++) z += al[ii] * zc[ii * 4 + jj] * be[jj];

    g_loss[b] = logf(z) - logf(u);   // = -log(u/z)
  }

  // ---- fused mean reduction: last block to finish does it ----
  __shared__ int is_last;
  if (tid == 0) {
    __threadfence();
    int prev = atomicAdd(&g_done_cnt, 1);
    is_last = (prev == NB - 1);
  }
  __syncthreads();
  if (is_last) {
    __threadfence();
    float v = g_loss[tid];
#pragma unroll
    for (int o = 16; o; o >>= 1) v += __shfl_xor_sync(0xFFFFFFFFu, v, o);
    __shared__ float sw[4];
    if ((tid & 31) == 0) sw[tid >> 5] = v;
    __syncthreads();
    if (tid == 0) {
      out[0] = (sw[0] + sw[1] + sw[2] + sw[3]) * (1.0f / 128.0f);
      atomicExch(&g_done_cnt, 0);   // reset for next graph replay
    }
  }
}

// =================================================================
extern "C" void kernel_launch(void* const* d_in, const int* in_sizes, int n_in,
                              void* d_out, int out_size) {
  const float* x      = (const float*)d_in[0];   // [128, 8, 2048]
  const int*   labels = (const int*)  d_in[1];   // [128, 8]
  const float* wa     = (const float*)d_in[2];   // [2048, 4]
  const float* wb     = (const float*)d_in[3];   // [2048, 4]
  const float* wv     = (const float*)d_in[4];   // [2048, 8192]
  float* out = (float*)d_out;

  prep_kernel<<<NB, 512>>>(x, wa, wb);
  gemm_kernel<<<2 * (NN / 64), 256>>>(wv);
  finalize_kernel<<<NB, 128>>>(labels, out);
}